// round 1
// baseline (speedup 1.0000x reference)
#include <cuda_runtime.h>

// Problem constants
#define CCH     12            // path channels: 1 time + 3 orig + 8 aug
#define TT      1024
#define NSTEP   1023
#define NCHUNK  11
#define CHLEN   93            // 11 * 93 = 1023
#define NPATH   64            // B(32) * GROUPS(2)
#define SIGC    1884          // 12 + 144 + 1728
#define L2OFF   12
#define L3OFF   156

// Scratch (no cudaMalloc allowed)
__device__ __align__(16) float g_part[NPATH * NCHUNK * SIGC]; // ~5.3 MB
__device__ __align__(16) float g_sig [NPATH * SIGC];          // ~0.5 MB

// ---------------------------------------------------------------------------
// Kernel 1: per-chunk partial signature.
// grid = (NCHUNK, NPATH), block = 160 (144 active compute threads).
// Thread (i,j) owns S3[i][j][0..11] + S2[i][j] + its private S1[i].
// Inner loop over 93 steps is sync-free.
// ---------------------------------------------------------------------------
__global__ __launch_bounds__(160) void chunk_kernel(const float* __restrict__ x,
                                                    const float* __restrict__ aug_w)
{
    __shared__ __align__(16) float dxsh[CHLEN * CCH];
    __shared__ float xsh[(CHLEN + 1) * 3];
    __shared__ float awsh[8 * 3];

    const int tid   = threadIdx.x;
    const int chunk = blockIdx.x;
    const int p     = blockIdx.y;        // path id = b*2 + g
    const int b     = p >> 1;
    const int g     = p & 1;
    const int t0    = chunk * CHLEN;

    // Stage x rows [t0, t0+CHLEN] and this group's aug weights
    for (int idx = tid; idx < (CHLEN + 1) * 3; idx += blockDim.x)
        xsh[idx] = x[(b * TT + t0) * 3 + idx];
    if (tid < 24) awsh[tid] = aug_w[g * 24 + tid];
    __syncthreads();

    // Precompute all increments dx[t][c] for the chunk.
    // c=0: time step (1/1023); c=1..3: raw x diffs; c=4..11: aug_w @ xdiff
    for (int idx = tid; idx < CHLEN * CCH; idx += blockDim.x) {
        int t = idx / CCH, c = idx % CCH;
        float xd0 = xsh[(t + 1) * 3 + 0] - xsh[t * 3 + 0];
        float xd1 = xsh[(t + 1) * 3 + 1] - xsh[t * 3 + 1];
        float xd2 = xsh[(t + 1) * 3 + 2] - xsh[t * 3 + 2];
        float v;
        if (c == 0)      v = 1.0f / 1023.0f;
        else if (c == 1) v = xd0;
        else if (c == 2) v = xd1;
        else if (c == 3) v = xd2;
        else {
            int e = c - 4;
            v = fmaf(awsh[e * 3 + 0], xd0,
                fmaf(awsh[e * 3 + 1], xd1,
                     awsh[e * 3 + 2] * xd2));
        }
        dxsh[idx] = v;
    }
    __syncthreads();

    if (tid < 144) {
        const int i = tid / CCH, j = tid % CCH;
        float S3v[12];
#pragma unroll
        for (int k = 0; k < 12; k++) S3v[k] = 0.0f;
        float S2ij = 0.0f;
        float s1i  = 0.0f;
        const float4* dx4 = (const float4*)dxsh;

        for (int t = 0; t < CHLEN; t++) {
            const float di = dxsh[t * CCH + i];
            const float dj = dxsh[t * CCH + j];
            const float4 d0 = dx4[t * 3 + 0];
            const float4 d1 = dx4[t * 3 + 1];
            const float4 d2 = dx4[t * 3 + 2];
            // S3[i][j][k] += d_i d_j d_k/6 + S1_i d_j d_k/2 + S2[i][j] d_k
            const float cc = fmaf(fmaf(di, 1.0f / 6.0f, 0.5f * s1i), dj, S2ij);
            S3v[0]  = fmaf(cc, d0.x, S3v[0]);
            S3v[1]  = fmaf(cc, d0.y, S3v[1]);
            S3v[2]  = fmaf(cc, d0.z, S3v[2]);
            S3v[3]  = fmaf(cc, d0.w, S3v[3]);
            S3v[4]  = fmaf(cc, d1.x, S3v[4]);
            S3v[5]  = fmaf(cc, d1.y, S3v[5]);
            S3v[6]  = fmaf(cc, d1.z, S3v[6]);
            S3v[7]  = fmaf(cc, d1.w, S3v[7]);
            S3v[8]  = fmaf(cc, d2.x, S3v[8]);
            S3v[9]  = fmaf(cc, d2.y, S3v[9]);
            S3v[10] = fmaf(cc, d2.z, S3v[10]);
            S3v[11] = fmaf(cc, d2.w, S3v[11]);
            // S2[i][j] += d_i d_j/2 + S1_i d_j   (old S1)
            S2ij = fmaf(fmaf(di, 0.5f, s1i), dj, S2ij);
            // S1_i += d_i
            s1i += di;
        }

        float* out = &g_part[(size_t)(p * NCHUNK + chunk) * SIGC];
        if (j == 0) out[i] = s1i;
        out[L2OFF + tid] = S2ij;
        float4* o4 = (float4*)(out + L3OFF + tid * 12);
        o4[0] = make_float4(S3v[0], S3v[1], S3v[2],  S3v[3]);
        o4[1] = make_float4(S3v[4], S3v[5], S3v[6],  S3v[7]);
        o4[2] = make_float4(S3v[8], S3v[9], S3v[10], S3v[11]);
    }
}

// ---------------------------------------------------------------------------
// Kernel 2: fold chunk partials left-to-right with Chen's identity.
// grid = NPATH, block = 160 (144 active). Accumulator A lives in registers
// (A3 row + A2ij per thread) + shared A1.
//   A3 += B3 + A1 (x) B2 + A2 (x) B1 ; A2 += B2 + A1 (x) B1 ; A1 += B1
// ---------------------------------------------------------------------------
__global__ __launch_bounds__(160) void combine_kernel()
{
    __shared__ __align__(16) float a1sh[12];
    __shared__ __align__(16) float b1sh[12];

    const int tid = threadIdx.x;
    const int p   = blockIdx.x;
    const int i   = tid / CCH, j = tid % CCH;
    const bool act = tid < 144;

    const float* base = &g_part[(size_t)p * NCHUNK * SIGC];

    float A3[12];
    float A2ij = 0.0f;
    if (act) {
        const float4* p4 = (const float4*)(base + L3OFF + tid * 12);
        float4 v0 = p4[0], v1 = p4[1], v2 = p4[2];
        A3[0] = v0.x; A3[1] = v0.y; A3[2]  = v0.z; A3[3]  = v0.w;
        A3[4] = v1.x; A3[5] = v1.y; A3[6]  = v1.z; A3[7]  = v1.w;
        A3[8] = v2.x; A3[9] = v2.y; A3[10] = v2.z; A3[11] = v2.w;
        A2ij = base[L2OFF + tid];
    }
    if (tid < 12) a1sh[tid] = base[tid];
    __syncthreads();

    for (int ch = 1; ch < NCHUNK; ch++) {
        const float* bp = base + (size_t)ch * SIGC;
        if (tid < 12) b1sh[tid] = bp[tid];
        __syncthreads();
        if (act) {
            const float a1i = a1sh[i];
            const float4* b2j4 = (const float4*)(bp + L2OFF + j * 12);
            const float4 q0 = b2j4[0], q1 = b2j4[1], q2 = b2j4[2];
            const float4* b34 = (const float4*)(bp + L3OFF + tid * 12);
            const float4 r0 = b34[0], r1 = b34[1], r2 = b34[2];
            const float4* b14 = (const float4*)b1sh;
            const float4 u0 = b14[0], u1 = b14[1], u2 = b14[2];

            // A3[k] += B3[i][j][k] + A1_i * B2[j][k] + A2ij * B1[k]  (old A1, old A2)
            A3[0]  += r0.x + fmaf(a1i, q0.x, A2ij * u0.x);
            A3[1]  += r0.y + fmaf(a1i, q0.y, A2ij * u0.y);
            A3[2]  += r0.z + fmaf(a1i, q0.z, A2ij * u0.z);
            A3[3]  += r0.w + fmaf(a1i, q0.w, A2ij * u0.w);
            A3[4]  += r1.x + fmaf(a1i, q1.x, A2ij * u1.x);
            A3[5]  += r1.y + fmaf(a1i, q1.y, A2ij * u1.y);
            A3[6]  += r1.z + fmaf(a1i, q1.z, A2ij * u1.z);
            A3[7]  += r1.w + fmaf(a1i, q1.w, A2ij * u1.w);
            A3[8]  += r2.x + fmaf(a1i, q2.x, A2ij * u2.x);
            A3[9]  += r2.y + fmaf(a1i, q2.y, A2ij * u2.y);
            A3[10] += r2.z + fmaf(a1i, q2.z, A2ij * u2.z);
            A3[11] += r2.w + fmaf(a1i, q2.w, A2ij * u2.w);

            // A2[i][j] += B2[i][j] + A1_i * B1_j  (old A1)
            A2ij += bp[L2OFF + i * 12 + j] + a1i * b1sh[j];
        }
        __syncthreads();
        if (tid < 12) a1sh[tid] += b1sh[tid];   // A1 += B1
    }
    __syncthreads();

    float* out = &g_sig[(size_t)p * SIGC];
    if (tid < 12) out[tid] = a1sh[tid];
    if (act) {
        out[L2OFF + tid] = A2ij;
        float4* o4 = (float4*)(out + L3OFF + tid * 12);
        o4[0] = make_float4(A3[0], A3[1], A3[2],  A3[3]);
        o4[1] = make_float4(A3[4], A3[5], A3[6],  A3[7]);
        o4[2] = make_float4(A3[8], A3[9], A3[10], A3[11]);
    }
}

// ---------------------------------------------------------------------------
// Kernel 3: out[b][o] = sigmoid( [sig(b,0) | sig(b,1)] . lin_w[o] + lin_b[o] )
// grid = 32 (batch), block = 256 (8 warps). Warp w handles outputs w, w+8, ...
// Coalesced lin_w reads; warp-shuffle reduction.
// ---------------------------------------------------------------------------
__global__ __launch_bounds__(256) void linear_kernel(const float* __restrict__ lin_w,
                                                     const float* __restrict__ lin_b,
                                                     float* __restrict__ out)
{
    const int b    = blockIdx.x;
    const int warp = threadIdx.x >> 5;
    const int lane = threadIdx.x & 31;
    const float* s0 = &g_sig[(size_t)(2 * b)     * SIGC];
    const float* s1 = &g_sig[(size_t)(2 * b + 1) * SIGC];

    for (int o = warp; o < 32; o += 8) {
        const float* w = lin_w + (size_t)o * (2 * SIGC);
        float acc = 0.0f;
        for (int f = lane; f < SIGC; f += 32) acc = fmaf(s0[f], w[f], acc);
        for (int f = lane; f < SIGC; f += 32) acc = fmaf(s1[f], w[SIGC + f], acc);
#pragma unroll
        for (int off = 16; off > 0; off >>= 1)
            acc += __shfl_down_sync(0xffffffffu, acc, off);
        if (lane == 0) {
            float z = acc + lin_b[o];
            out[b * 32 + o] = 1.0f / (1.0f + expf(-z));
        }
    }
}

// ---------------------------------------------------------------------------
extern "C" void kernel_launch(void* const* d_in, const int* in_sizes, int n_in,
                              void* d_out, int out_size)
{
    const float* x     = (const float*)d_in[0];  // (32,1024,3)
    const float* aug_w = (const float*)d_in[1];  // (2,8,3)
    // d_in[2] = aug_b : unused (signature is translation-invariant)
    const float* lin_w = (const float*)d_in[3];  // (32, 3768)
    const float* lin_b = (const float*)d_in[4];  // (32,)
    float* out = (float*)d_out;                  // (32,32) float32

    dim3 grid1(NCHUNK, NPATH);
    chunk_kernel<<<grid1, 160>>>(x, aug_w);
    combine_kernel<<<NPATH, 160>>>();
    linear_kernel<<<32, 256>>>(lin_w, lin_b, out);
}

// round 2
// speedup vs baseline: 1.1018x; 1.1018x over previous
#include <cuda_runtime.h>

// Problem constants
#define CCH     12            // path channels: 1 time + 3 orig + 8 aug
#define TT      1024
#define NSTEP   1023
#define NCHUNK  33
#define CHLEN   31            // 33 * 31 = 1023
#define NPATH   64            // B(32) * GROUPS(2)
#define SIGC    1884          // 12 + 144 + 1728
#define L2OFF   12
#define L3OFF   156

// Scratch (no cudaMalloc allowed)
__device__ __align__(16) float g_part[NPATH * NCHUNK * SIGC]; // ~15.9 MB
__device__ __align__(16) float g_sig [NPATH * SIGC];          // ~0.5 MB

// ---------------------------------------------------------------------------
// Kernel 1: per-chunk partial signature.
// grid = (NCHUNK, NPATH), block = 160 (144 active compute threads).
// Thread (i,j) owns S3[i][j][0..11] + S2[i][j] + its private S1[i].
// Inner loop over 31 steps is sync-free.
// ---------------------------------------------------------------------------
__global__ __launch_bounds__(160) void chunk_kernel(const float* __restrict__ x,
                                                    const float* __restrict__ aug_w)
{
    __shared__ __align__(16) float dxsh[CHLEN * CCH];
    __shared__ float xsh[(CHLEN + 1) * 3];
    __shared__ float awsh[8 * 3];

    const int tid   = threadIdx.x;
    const int chunk = blockIdx.x;
    const int p     = blockIdx.y;        // path id = b*2 + g
    const int b     = p >> 1;
    const int g     = p & 1;
    const int t0    = chunk * CHLEN;

    // Stage x rows [t0, t0+CHLEN] and this group's aug weights
    for (int idx = tid; idx < (CHLEN + 1) * 3; idx += blockDim.x)
        xsh[idx] = x[(b * TT + t0) * 3 + idx];
    if (tid < 24) awsh[tid] = aug_w[g * 24 + tid];
    __syncthreads();

    // Precompute all increments dx[t][c] for the chunk.
    for (int idx = tid; idx < CHLEN * CCH; idx += blockDim.x) {
        int t = idx / CCH, c = idx % CCH;
        float xd0 = xsh[(t + 1) * 3 + 0] - xsh[t * 3 + 0];
        float xd1 = xsh[(t + 1) * 3 + 1] - xsh[t * 3 + 1];
        float xd2 = xsh[(t + 1) * 3 + 2] - xsh[t * 3 + 2];
        float v;
        if (c == 0)      v = 1.0f / 1023.0f;
        else if (c == 1) v = xd0;
        else if (c == 2) v = xd1;
        else if (c == 3) v = xd2;
        else {
            int e = c - 4;
            v = fmaf(awsh[e * 3 + 0], xd0,
                fmaf(awsh[e * 3 + 1], xd1,
                     awsh[e * 3 + 2] * xd2));
        }
        dxsh[idx] = v;
    }
    __syncthreads();

    if (tid < 144) {
        const int i = tid / CCH, j = tid % CCH;
        float S3v[12];
#pragma unroll
        for (int k = 0; k < 12; k++) S3v[k] = 0.0f;
        float S2ij = 0.0f;
        float s1i  = 0.0f;
        const float4* dx4 = (const float4*)dxsh;

#pragma unroll 31
        for (int t = 0; t < CHLEN; t++) {
            const float di = dxsh[t * CCH + i];
            const float dj = dxsh[t * CCH + j];
            const float4 d0 = dx4[t * 3 + 0];
            const float4 d1 = dx4[t * 3 + 1];
            const float4 d2 = dx4[t * 3 + 2];
            // S3[i][j][k] += (d_i/6 + S1_i/2) d_j d_k + S2[i][j] d_k
            const float cc = fmaf(fmaf(di, 1.0f / 6.0f, 0.5f * s1i), dj, S2ij);
            S3v[0]  = fmaf(cc, d0.x, S3v[0]);
            S3v[1]  = fmaf(cc, d0.y, S3v[1]);
            S3v[2]  = fmaf(cc, d0.z, S3v[2]);
            S3v[3]  = fmaf(cc, d0.w, S3v[3]);
            S3v[4]  = fmaf(cc, d1.x, S3v[4]);
            S3v[5]  = fmaf(cc, d1.y, S3v[5]);
            S3v[6]  = fmaf(cc, d1.z, S3v[6]);
            S3v[7]  = fmaf(cc, d1.w, S3v[7]);
            S3v[8]  = fmaf(cc, d2.x, S3v[8]);
            S3v[9]  = fmaf(cc, d2.y, S3v[9]);
            S3v[10] = fmaf(cc, d2.z, S3v[10]);
            S3v[11] = fmaf(cc, d2.w, S3v[11]);
            // S2[i][j] += d_i d_j/2 + S1_i d_j   (old S1)
            S2ij = fmaf(fmaf(di, 0.5f, s1i), dj, S2ij);
            s1i += di;
        }

        float* out = &g_part[(size_t)(p * NCHUNK + chunk) * SIGC];
        if (j == 0) out[i] = s1i;
        out[L2OFF + tid] = S2ij;
        float4* o4 = (float4*)(out + L3OFF + tid * 12);
        o4[0] = make_float4(S3v[0], S3v[1], S3v[2],  S3v[3]);
        o4[1] = make_float4(S3v[4], S3v[5], S3v[6],  S3v[7]);
        o4[2] = make_float4(S3v[8], S3v[9], S3v[10], S3v[11]);
    }
}

// ---------------------------------------------------------------------------
// Kernel 2: fold chunk partials left-to-right with Chen's identity.
// grid = NPATH, block = 448 (432 active). Thread = (i, j, k-quad kg):
// owns A3[i][j][4kg..4kg+3] (float4) + redundant A2ij + redundant a1i.
// NO barriers in the fold loop -> loads of future folds can be hoisted (MLP).
//   A3 += B3 + A1 (x) B2 + A2 (x) B1 ; A2 += B2 + A1 (x) B1 ; A1 += B1
// ---------------------------------------------------------------------------
__global__ __launch_bounds__(448) void combine_kernel()
{
    const int tid = threadIdx.x;
    if (tid >= 432) return;
    const int t144 = tid / 3;           // (i,j) index
    const int kg   = tid - 3 * t144;    // k-quad 0..2
    const int i    = t144 / CCH;
    const int j    = t144 - CCH * i;
    const int p    = blockIdx.x;

    const float* __restrict__ base = &g_part[(size_t)p * NCHUNK * SIGC];

    // Init from chunk 0
    float4 A3   = *(const float4*)(base + L3OFF + t144 * 12 + kg * 4);
    float  A2ij = base[L2OFF + t144];
    float  a1i  = base[i];

#pragma unroll 4
    for (int ch = 1; ch < NCHUNK; ch++) {
        const float* __restrict__ bp = base + (size_t)ch * SIGC;
        const float4 u   = *(const float4*)(bp + kg * 4);                     // B1 quad
        const float  b1i = bp[i];
        const float  b1j = bp[j];
        const float4 q   = *(const float4*)(bp + L2OFF + j * 12 + kg * 4);    // B2[j] quad
        const float  b2  = bp[L2OFF + i * CCH + j];
        const float4 r   = *(const float4*)(bp + L3OFF + t144 * 12 + kg * 4); // B3 quad

        // old A1, old A2
        A3.x += r.x; A3.x = fmaf(a1i, q.x, A3.x); A3.x = fmaf(A2ij, u.x, A3.x);
        A3.y += r.y; A3.y = fmaf(a1i, q.y, A3.y); A3.y = fmaf(A2ij, u.y, A3.y);
        A3.z += r.z; A3.z = fmaf(a1i, q.z, A3.z); A3.z = fmaf(A2ij, u.z, A3.z);
        A3.w += r.w; A3.w = fmaf(a1i, q.w, A3.w); A3.w = fmaf(A2ij, u.w, A3.w);
        A2ij += b2 + a1i * b1j;   // old A1
        a1i  += b1i;
    }

    float* out = &g_sig[(size_t)p * SIGC];
    *(float4*)(out + L3OFF + t144 * 12 + kg * 4) = A3;
    if (kg == 0) {
        out[L2OFF + t144] = A2ij;
        if (j == 0) out[i] = a1i;
    }
}

// ---------------------------------------------------------------------------
// Kernel 3: out[b][o] = sigmoid( sig(b) . lin_w[o] + lin_b[o] )
// sig(b) = [sig path 2b | sig path 2b+1] is contiguous (3768 floats).
// grid = 32 (batch), block = 256 (8 warps). Warp w -> outputs w, w+8, ...
// float4 loads, warp-shuffle reduction.
// ---------------------------------------------------------------------------
__global__ __launch_bounds__(256) void linear_kernel(const float* __restrict__ lin_w,
                                                     const float* __restrict__ lin_b,
                                                     float* __restrict__ out)
{
    const int b    = blockIdx.x;
    const int warp = threadIdx.x >> 5;
    const int lane = threadIdx.x & 31;
    const float4* __restrict__ s4 = (const float4*)(&g_sig[(size_t)b * 2 * SIGC]);
    const int NV = (2 * SIGC) / 4;   // 942 float4s

    for (int o = warp; o < 32; o += 8) {
        const float4* __restrict__ w4 = (const float4*)(lin_w + (size_t)o * 2 * SIGC);
        float ax = 0.0f, ay = 0.0f, az = 0.0f, aw = 0.0f;
        for (int f = lane; f < NV; f += 32) {
            float4 sv = s4[f];
            float4 wv = w4[f];
            ax = fmaf(sv.x, wv.x, ax);
            ay = fmaf(sv.y, wv.y, ay);
            az = fmaf(sv.z, wv.z, az);
            aw = fmaf(sv.w, wv.w, aw);
        }
        float acc = (ax + ay) + (az + aw);
#pragma unroll
        for (int off = 16; off > 0; off >>= 1)
            acc += __shfl_down_sync(0xffffffffu, acc, off);
        if (lane == 0) {
            float z = acc + lin_b[o];
            out[b * 32 + o] = 1.0f / (1.0f + expf(-z));
        }
    }
}

// ---------------------------------------------------------------------------
extern "C" void kernel_launch(void* const* d_in, const int* in_sizes, int n_in,
                              void* d_out, int out_size)
{
    const float* x     = (const float*)d_in[0];  // (32,1024,3)
    const float* aug_w = (const float*)d_in[1];  // (2,8,3)
    // d_in[2] = aug_b : unused (signature is translation-invariant)
    const float* lin_w = (const float*)d_in[3];  // (32, 3768)
    const float* lin_b = (const float*)d_in[4];  // (32,)
    float* out = (float*)d_out;                  // (32,32) float32

    dim3 grid1(NCHUNK, NPATH);
    chunk_kernel<<<grid1, 160>>>(x, aug_w);
    combine_kernel<<<NPATH, 448>>>();
    linear_kernel<<<32, 256>>>(lin_w, lin_b, out);
}

// round 3
// speedup vs baseline: 1.4377x; 1.3048x over previous
#include <cuda_runtime.h>

// Problem constants
#define CCH     12            // path channels: 1 time + 3 orig + 8 aug
#define TT      1024
#define NSTEP   1023
#define NCHUNK  31
#define CHLEN   33            // 31 * 33 = 1023
#define NPATH   64            // B(32) * GROUPS(2)
#define SIGC    1884          // 12 + 144 + 1728
#define L2OFF   12
#define L3OFF   156
#define TSTRIDE 36            // padded t-stride of transposed dx (16B aligned)

// Scratch (no cudaMalloc allowed)
__device__ __align__(16) float g_part[NPATH * NCHUNK * SIGC]; // ~15 MB

// ---------------------------------------------------------------------------
// Kernel 1: per-chunk partial signature.
// grid = (NCHUNK, NPATH), block = 160 (144 active compute threads).
// Thread (i,j) owns S3[i][j][0..11] + S2[i][j] + private S1[i].
// dx kept in TWO layouts: [t][c] (for broadcast float4 k-loads) and
// transposed [c][t] (so di/dj for 4 consecutive steps come from ONE LDS.128).
// ---------------------------------------------------------------------------
__global__ __launch_bounds__(160) void chunk_kernel(const float* __restrict__ x,
                                                    const float* __restrict__ aug_w)
{
    __shared__ __align__(16) float dxsh[CHLEN * CCH];       // [t][c]
    __shared__ __align__(16) float dxT [CCH * TSTRIDE];     // [c][t_padded]
    __shared__ float xsh[(CHLEN + 1) * 3];
    __shared__ float awsh[8 * 3];

    const int tid   = threadIdx.x;
    const int chunk = blockIdx.x;
    const int p     = blockIdx.y;        // path id = b*2 + g
    const int b     = p >> 1;
    const int g     = p & 1;
    const int t0    = chunk * CHLEN;

    for (int idx = tid; idx < (CHLEN + 1) * 3; idx += blockDim.x)
        xsh[idx] = x[(b * TT + t0) * 3 + idx];
    if (tid < 24) awsh[tid] = aug_w[g * 24 + tid];
    __syncthreads();

    // Precompute increments into both layouts.
    for (int idx = tid; idx < CHLEN * CCH; idx += blockDim.x) {
        int t = idx / CCH, c = idx - t * CCH;
        float xd0 = xsh[(t + 1) * 3 + 0] - xsh[t * 3 + 0];
        float xd1 = xsh[(t + 1) * 3 + 1] - xsh[t * 3 + 1];
        float xd2 = xsh[(t + 1) * 3 + 2] - xsh[t * 3 + 2];
        float v;
        if (c == 0)      v = 1.0f / 1023.0f;
        else if (c == 1) v = xd0;
        else if (c == 2) v = xd1;
        else if (c == 3) v = xd2;
        else {
            int e = c - 4;
            v = fmaf(awsh[e * 3 + 0], xd0,
                fmaf(awsh[e * 3 + 1], xd1,
                     awsh[e * 3 + 2] * xd2));
        }
        dxsh[idx] = v;
        dxT[c * TSTRIDE + t] = v;
    }
    __syncthreads();

    if (tid < 144) {
        const int i = tid / CCH, j = tid - CCH * (tid / CCH);
        float S3[12];
#pragma unroll
        for (int k = 0; k < 12; k++) S3[k] = 0.0f;
        float S2 = 0.0f;
        float s1 = 0.0f;
        const float4* __restrict__ dxq = (const float4*)dxsh;
        const float4* __restrict__ diT = (const float4*)(dxT + i * TSTRIDE);
        const float4* __restrict__ djT = (const float4*)(dxT + j * TSTRIDE);

#define SIG_STEP(tq, di_, dj_) {                                              \
        const float4 d0 = dxq[(tq) * 3 + 0];                                  \
        const float4 d1 = dxq[(tq) * 3 + 1];                                  \
        const float4 d2 = dxq[(tq) * 3 + 2];                                  \
        const float cc = fmaf(fmaf((di_), 1.0f/6.0f, 0.5f * s1), (dj_), S2);  \
        S3[0]  = fmaf(cc, d0.x, S3[0]);                                       \
        S3[1]  = fmaf(cc, d0.y, S3[1]);                                       \
        S3[2]  = fmaf(cc, d0.z, S3[2]);                                       \
        S3[3]  = fmaf(cc, d0.w, S3[3]);                                       \
        S3[4]  = fmaf(cc, d1.x, S3[4]);                                       \
        S3[5]  = fmaf(cc, d1.y, S3[5]);                                       \
        S3[6]  = fmaf(cc, d1.z, S3[6]);                                       \
        S3[7]  = fmaf(cc, d1.w, S3[7]);                                       \
        S3[8]  = fmaf(cc, d2.x, S3[8]);                                       \
        S3[9]  = fmaf(cc, d2.y, S3[9]);                                       \
        S3[10] = fmaf(cc, d2.z, S3[10]);                                      \
        S3[11] = fmaf(cc, d2.w, S3[11]);                                      \
        S2 = fmaf(fmaf((di_), 0.5f, s1), (dj_), S2);                          \
        s1 += (di_); }

#pragma unroll 4
        for (int tb = 0; tb < 8; tb++) {
            const float4 di4 = diT[tb];
            const float4 dj4 = djT[tb];
            SIG_STEP(tb * 4 + 0, di4.x, dj4.x);
            SIG_STEP(tb * 4 + 1, di4.y, dj4.y);
            SIG_STEP(tb * 4 + 2, di4.z, dj4.z);
            SIG_STEP(tb * 4 + 3, di4.w, dj4.w);
        }
        {   // remainder step t = 32
            const float di = dxT[i * TSTRIDE + 32];
            const float dj = dxT[j * TSTRIDE + 32];
            SIG_STEP(32, di, dj);
        }
#undef SIG_STEP

        float* out = &g_part[(size_t)(p * NCHUNK + chunk) * SIGC];
        if (j == 0) out[i] = s1;
        out[L2OFF + tid] = S2;
        float4* o4 = (float4*)(out + L3OFF + tid * 12);
        o4[0] = make_float4(S3[0], S3[1], S3[2],  S3[3]);
        o4[1] = make_float4(S3[4], S3[5], S3[6],  S3[7]);
        o4[2] = make_float4(S3[8], S3[9], S3[10], S3[11]);
    }
}

// ---------------------------------------------------------------------------
// Kernel 2 (fused): per-batch combine (both groups) into SHARED sig, then
// GEMV + sigmoid. grid = 32 (batch), block = 1024.
// Phase A: threads 0..863 = 2 paths x 432; thread = (grp, i, j, k-quad kg),
//          no barriers inside the fold loop.
// Phase B: 32 warps; warp o computes out[b][o].
// ---------------------------------------------------------------------------
__global__ __launch_bounds__(1024) void combine_linear_kernel(
        const float* __restrict__ lin_w,
        const float* __restrict__ lin_b,
        float* __restrict__ out)
{
    __shared__ __align__(16) float sig[2 * SIGC];   // 3768 floats = 15 KB

    const int tid = threadIdx.x;
    const int b   = blockIdx.x;

    if (tid < 864) {
        const int grp  = tid / 432;
        const int u    = tid - 432 * grp;
        const int t144 = u / 3;
        const int kg   = u - 3 * t144;
        const int i    = t144 / CCH;
        const int j    = t144 - CCH * i;
        const int p    = 2 * b + grp;

        const float* __restrict__ base = &g_part[(size_t)p * NCHUNK * SIGC];

        float4 A3   = *(const float4*)(base + L3OFF + t144 * 12 + kg * 4);
        float  A2ij = base[L2OFF + t144];
        float  a1i  = base[i];

#pragma unroll 2
        for (int ch = 1; ch < NCHUNK; ch++) {
            const float* __restrict__ bp = base + (size_t)ch * SIGC;
            const float4 u4  = *(const float4*)(bp + kg * 4);                     // B1 quad
            const float  b1i = bp[i];
            const float  b1j = bp[j];
            const float4 q   = *(const float4*)(bp + L2OFF + j * 12 + kg * 4);    // B2[j] quad
            const float  b2  = bp[L2OFF + i * CCH + j];
            const float4 r   = *(const float4*)(bp + L3OFF + t144 * 12 + kg * 4); // B3 quad

            // old A1, old A2
            A3.x += r.x; A3.x = fmaf(a1i, q.x, A3.x); A3.x = fmaf(A2ij, u4.x, A3.x);
            A3.y += r.y; A3.y = fmaf(a1i, q.y, A3.y); A3.y = fmaf(A2ij, u4.y, A3.y);
            A3.z += r.z; A3.z = fmaf(a1i, q.z, A3.z); A3.z = fmaf(A2ij, u4.z, A3.z);
            A3.w += r.w; A3.w = fmaf(a1i, q.w, A3.w); A3.w = fmaf(A2ij, u4.w, A3.w);
            A2ij += b2 + a1i * b1j;   // old A1
            a1i  += b1i;
        }

        float* so = &sig[grp * SIGC];
        *(float4*)(so + L3OFF + t144 * 12 + kg * 4) = A3;
        if (kg == 0) {
            so[L2OFF + t144] = A2ij;
            if (j == 0) so[i] = a1i;
        }
    }
    __syncthreads();

    // Phase B: GEMV + sigmoid. Warp o handles output o.
    const int o    = tid >> 5;
    const int lane = tid & 31;
    const float4* __restrict__ s4 = (const float4*)sig;
    const float4* __restrict__ w4 = (const float4*)(lin_w + (size_t)o * 2 * SIGC);
    const int NV = (2 * SIGC) / 4;   // 942

    float ax = 0.0f, ay = 0.0f, az = 0.0f, aw = 0.0f;
    for (int f = lane; f < NV; f += 32) {
        float4 sv = s4[f];
        float4 wv = w4[f];
        ax = fmaf(sv.x, wv.x, ax);
        ay = fmaf(sv.y, wv.y, ay);
        az = fmaf(sv.z, wv.z, az);
        aw = fmaf(sv.w, wv.w, aw);
    }
    float acc = (ax + ay) + (az + aw);
#pragma unroll
    for (int off = 16; off > 0; off >>= 1)
        acc += __shfl_down_sync(0xffffffffu, acc, off);
    if (lane == 0) {
        float z = acc + lin_b[o];
        out[b * 32 + o] = 1.0f / (1.0f + expf(-z));
    }
}

// ---------------------------------------------------------------------------
extern "C" void kernel_launch(void* const* d_in, const int* in_sizes, int n_in,
                              void* d_out, int out_size)
{
    const float* x     = (const float*)d_in[0];  // (32,1024,3)
    const float* aug_w = (const float*)d_in[1];  // (2,8,3)
    // d_in[2] = aug_b : unused (signature is translation-invariant)
    const float* lin_w = (const float*)d_in[3];  // (32, 3768)
    const float* lin_b = (const float*)d_in[4];  // (32,)
    float* out = (float*)d_out;                  // (32,32) float32

    dim3 grid1(NCHUNK, NPATH);
    chunk_kernel<<<grid1, 160>>>(x, aug_w);
    combine_linear_kernel<<<32, 1024>>>(lin_w, lin_b, out);
}